// round 2
// baseline (speedup 1.0000x reference)
#include <cuda_runtime.h>
#include <cuda_fp16.h>
#include <cstdint>
#include <cstddef>

#define IN_F   4096
#define OUT_F  11008
#define M_DIM  8192
#define K_DIM  4096
#define N_DIM  11008

#define BM 128
#define BN 128
#define BK 32
#define ASTR 40   // BK + 8 halfword skew -> conflict-free ldmatrix

__constant__ float c_nf4[16] = {
    -1.0f, -0.6961928009986877f, -0.5250730514526367f, -0.39491748809814453f,
    -0.28444138169288635f, -0.18477343022823334f, -0.09105003625154495f, 0.0f,
    0.07958029955625534f, 0.16093020141124725f, 0.24611230194568634f,
    0.33791524171829224f, 0.44070982933044434f, 0.5626170039176941f,
    0.7229568362236023f, 1.0f };

// scratch: dequantized W (fp16) and converted x (fp16)
__device__ __half g_W[(size_t)OUT_F * IN_F];
__device__ __half g_X[(size_t)M_DIM * K_DIM];

// ---------------------------------------------------------------------------
// Kernel 1: NF4 dequant  W[n,k] = codebook[codes[n,k]] * absmax[(n*K+k)/64]
// Each thread handles 8 elements (2x int4 code loads, 1x uint4 half store).
// ---------------------------------------------------------------------------
__global__ void dequant_w_kernel(const int* __restrict__ codes,
                                 const float* __restrict__ absmax) {
    size_t t = (size_t)blockIdx.x * blockDim.x + threadIdx.x;
    const size_t total8 = (size_t)OUT_F * IN_F / 8;
    if (t >= total8) return;
    float am = absmax[t >> 3];                  // block of 64 = 8 threads
    int4 c0 = ((const int4*)codes)[2 * t];
    int4 c1 = ((const int4*)codes)[2 * t + 1];
    __half h[8];
    h[0] = __float2half(c_nf4[c0.x] * am);
    h[1] = __float2half(c_nf4[c0.y] * am);
    h[2] = __float2half(c_nf4[c0.z] * am);
    h[3] = __float2half(c_nf4[c0.w] * am);
    h[4] = __float2half(c_nf4[c1.x] * am);
    h[5] = __float2half(c_nf4[c1.y] * am);
    h[6] = __float2half(c_nf4[c1.z] * am);
    h[7] = __float2half(c_nf4[c1.w] * am);
    ((uint4*)g_W)[t] = *(const uint4*)h;
}

// ---------------------------------------------------------------------------
// Kernel 2: x fp32 -> fp16
// ---------------------------------------------------------------------------
__global__ void convert_x_kernel(const float* __restrict__ x) {
    size_t t = (size_t)blockIdx.x * blockDim.x + threadIdx.x;
    const size_t total8 = (size_t)M_DIM * K_DIM / 8;
    if (t >= total8) return;
    float4 a = ((const float4*)x)[2 * t];
    float4 b = ((const float4*)x)[2 * t + 1];
    __half h[8];
    h[0] = __float2half(a.x); h[1] = __float2half(a.y);
    h[2] = __float2half(a.z); h[3] = __float2half(a.w);
    h[4] = __float2half(b.x); h[5] = __float2half(b.y);
    h[6] = __float2half(b.z); h[7] = __float2half(b.w);
    ((uint4*)g_X)[t] = *(const uint4*)h;
}

// ---------------------------------------------------------------------------
// Kernel 3: fp16 GEMM  out[m,n] = sum_k X[m,k] * W[n,k], fp32 accumulate.
// CTA tile 128x128x32, 8 warps (2m x 4n), warp tile 64x32.
// cp.async double-buffered; ldmatrix + mma.sync.m16n8k16.
// All dims divide tile sizes exactly: no bounds checks.
// ---------------------------------------------------------------------------
__device__ __forceinline__ void cp16(void* dst, const void* src) {
    uint32_t d = (uint32_t)__cvta_generic_to_shared(dst);
    asm volatile("cp.async.cg.shared.global [%0], [%1], 16;" :: "r"(d), "l"(src) : "memory");
}

__global__ __launch_bounds__(256) void gemm_f16_kernel(float* __restrict__ out) {
    __shared__ __half As[2][BM * ASTR];
    __shared__ __half Bs[2][BN * ASTR];

    const int tid  = threadIdx.x;
    const int lane = tid & 31;
    const int warp = tid >> 5;
    const int wm   = warp >> 2;      // 0..1
    const int wn   = warp & 3;       // 0..3

    const size_t bm0 = (size_t)blockIdx.y * BM;
    const size_t bn0 = (size_t)blockIdx.x * BN;

    const __half* Ag = g_X + bm0 * K_DIM;
    const __half* Bg = g_W + bn0 * K_DIM;

    // global->shared load mapping: 256 threads, each loads 2x16B per tile
    const int lrow = tid >> 2;            // 0..63
    const int lcol = (tid & 3) * 8;       // 0,8,16,24 halfwords

    float c[4][4][4];
#pragma unroll
    for (int i = 0; i < 4; ++i)
#pragma unroll
        for (int j = 0; j < 4; ++j)
#pragma unroll
            for (int r = 0; r < 4; ++r) c[i][j][r] = 0.0f;

    // prologue: stage 0
    cp16(&As[0][lrow * ASTR + lcol],        Ag + (size_t)lrow * K_DIM + lcol);
    cp16(&As[0][(lrow + 64) * ASTR + lcol], Ag + (size_t)(lrow + 64) * K_DIM + lcol);
    cp16(&Bs[0][lrow * ASTR + lcol],        Bg + (size_t)lrow * K_DIM + lcol);
    cp16(&Bs[0][(lrow + 64) * ASTR + lcol], Bg + (size_t)(lrow + 64) * K_DIM + lcol);
    asm volatile("cp.async.commit_group;" ::: "memory");

    const int NKT = K_DIM / BK;   // 128
    int buf = 0;

    for (int kt = 0; kt < NKT; ++kt) {
        asm volatile("cp.async.wait_group 0;" ::: "memory");
        __syncthreads();

        if (kt + 1 < NKT) {
            const __half* a = Ag + (size_t)(kt + 1) * BK;
            const __half* b = Bg + (size_t)(kt + 1) * BK;
            int nb = buf ^ 1;
            cp16(&As[nb][lrow * ASTR + lcol],        a + (size_t)lrow * K_DIM + lcol);
            cp16(&As[nb][(lrow + 64) * ASTR + lcol], a + (size_t)(lrow + 64) * K_DIM + lcol);
            cp16(&Bs[nb][lrow * ASTR + lcol],        b + (size_t)lrow * K_DIM + lcol);
            cp16(&Bs[nb][(lrow + 64) * ASTR + lcol], b + (size_t)(lrow + 64) * K_DIM + lcol);
            asm volatile("cp.async.commit_group;" ::: "memory");
        }

#pragma unroll
        for (int ks = 0; ks < 2; ++ks) {
            const int k0 = ks * 16;
            uint32_t af[4][4];
            uint32_t bf[4][2];
#pragma unroll
            for (int mi = 0; mi < 4; ++mi) {
                const __half* p = &As[buf][(wm * 64 + mi * 16 + (lane & 15)) * ASTR
                                           + k0 + (lane >> 4) * 8];
                uint32_t addr = (uint32_t)__cvta_generic_to_shared(p);
                asm volatile("ldmatrix.sync.aligned.m8n8.x4.shared.b16 {%0,%1,%2,%3}, [%4];"
                             : "=r"(af[mi][0]), "=r"(af[mi][1]), "=r"(af[mi][2]), "=r"(af[mi][3])
                             : "r"(addr));
            }
#pragma unroll
            for (int ni = 0; ni < 4; ++ni) {
                const __half* p = &Bs[buf][(wn * 32 + ni * 8 + (lane & 7)) * ASTR
                                           + k0 + ((lane >> 3) & 1) * 8];
                uint32_t addr = (uint32_t)__cvta_generic_to_shared(p);
                asm volatile("ldmatrix.sync.aligned.m8n8.x2.shared.b16 {%0,%1}, [%2];"
                             : "=r"(bf[ni][0]), "=r"(bf[ni][1])
                             : "r"(addr));
            }
#pragma unroll
            for (int mi = 0; mi < 4; ++mi) {
#pragma unroll
                for (int ni = 0; ni < 4; ++ni) {
                    asm volatile(
                        "mma.sync.aligned.m16n8k16.row.col.f32.f16.f16.f32 "
                        "{%0,%1,%2,%3}, {%4,%5,%6,%7}, {%8,%9}, {%0,%1,%2,%3};"
                        : "+f"(c[mi][ni][0]), "+f"(c[mi][ni][1]),
                          "+f"(c[mi][ni][2]), "+f"(c[mi][ni][3])
                        : "r"(af[mi][0]), "r"(af[mi][1]), "r"(af[mi][2]), "r"(af[mi][3]),
                          "r"(bf[ni][0]), "r"(bf[ni][1]));
                }
            }
        }
        buf ^= 1;
    }

    // epilogue: direct fp32 stores (float2 per row-fragment)
#pragma unroll
    for (int mi = 0; mi < 4; ++mi) {
        const int r0 = (int)bm0 + wm * 64 + mi * 16 + (lane >> 2);
#pragma unroll
        for (int ni = 0; ni < 4; ++ni) {
            const int col = (int)bn0 + wn * 32 + ni * 8 + (lane & 3) * 2;
            float2 v0 = make_float2(c[mi][ni][0], c[mi][ni][1]);
            float2 v1 = make_float2(c[mi][ni][2], c[mi][ni][3]);
            *(float2*)&out[(size_t)r0 * N_DIM + col]       = v0;
            *(float2*)&out[(size_t)(r0 + 8) * N_DIM + col] = v1;
        }
    }
}

// ---------------------------------------------------------------------------
extern "C" void kernel_launch(void* const* d_in, const int* in_sizes, int n_in,
                              void* d_out, int out_size) {
    const float* x      = (const float*)d_in[0];
    const int*   codes  = (const int*)d_in[1];
    const float* absmax = (const float*)d_in[2];
    float*       out    = (float*)d_out;

    {
        size_t t8 = (size_t)OUT_F * IN_F / 8;
        dequant_w_kernel<<<(unsigned)((t8 + 255) / 256), 256>>>(codes, absmax);
    }
    {
        size_t t8 = (size_t)M_DIM * K_DIM / 8;
        convert_x_kernel<<<(unsigned)((t8 + 255) / 256), 256>>>(x);
    }
    gemm_f16_kernel<<<dim3(N_DIM / BN, M_DIM / BM), 256>>>(out);
}